// round 11
// baseline (speedup 1.0000x reference)
#include <cuda_runtime.h>
#include <cstdint>
#include <math.h>

// ---- problem constants ----
#define BATCH    16
#define KTUP     16384
#define ADDS     32
#define NP       36          // 2^2 + 32 candidates per point
#define DIM      65536       // IN_DIM == OUT_DIM

// 4MB precomputed-parameter scratch: {m0, m1, nh, val} per (b, k)
__device__ float4 g_params[BATCH * KTUP];

// =====================================================================
// threefry-2x32, 20 rounds, exactly as jax._src.prng (key = (0, 42)).
// Partitionable mode: counter = (0, flat_index), bits = o0 ^ o1.
// =====================================================================
__device__ __forceinline__ void threefry2x32_42(uint32_t c0, uint32_t c1,
                                                uint32_t& o0, uint32_t& o1) {
    const uint32_t ks0 = 0u;
    const uint32_t ks1 = 42u;
    const uint32_t ks2 = 0x1BD11BDAu ^ 0u ^ 42u;
    uint32_t x0 = c0 + ks0;
    uint32_t x1 = c1 + ks1;
#define TF_R(rot) { x0 += x1; x1 = __funnelshift_l(x1, x1, rot); x1 ^= x0; }
    TF_R(13) TF_R(15) TF_R(26) TF_R(6)   x0 += ks1; x1 += ks2 + 1u;
    TF_R(17) TF_R(29) TF_R(16) TF_R(24)  x0 += ks2; x1 += ks0 + 2u;
    TF_R(13) TF_R(15) TF_R(26) TF_R(6)   x0 += ks0; x1 += ks1 + 3u;
    TF_R(17) TF_R(29) TF_R(16) TF_R(24)  x0 += ks1; x1 += ks2 + 4u;
    TF_R(13) TF_R(15) TF_R(26) TF_R(6)   x0 += ks2; x1 += ks0 + 5u;
#undef TF_R
    o0 = x0; o1 = x1;
}

__device__ __forceinline__ uint32_t jax_random_bits32(uint32_t e) {
    uint32_t o0, o1;
    threefry2x32_42(0u, e, o0, o1);
    return o0 ^ o1;
}

// bits -> JAX index, bit-exact, 1 FFMA (Sterbenz + exponent-exact scale;
// proof in round 10, validated by identical rel_err).
__device__ __forceinline__ int bits_to_idx(uint32_t bits) {
    const float C = 0.999999f * 65536.0f;
    float v = __uint_as_float((bits >> 9) | 0x3f800000u);
    return (int)__fmaf_rn(v, C, -C);
}

// ---- sigmoid / softplus: IDENTICAL arithmetic to passing rounds 4-10 ----
__device__ __forceinline__ float xla_sigmoid(float v) {
    float e = expf(-v);
    return __fdiv_rn(1.0f, __fadd_rn(1.0f, e));
}
__device__ __forceinline__ float softplus_f(float v) {
    return fmaxf(v, 0.0f) + log1pf(__expf(-fabsf(v)));
}

// Warp sum via integer redux (f32 redux does not exist on sm_103).
// Fixed point 2^24: sum <= 36 -> max 6.0e8 < 2^31. Validated rounds 9-10.
#define FIXPT 16777216.0f
__device__ __forceinline__ float warp_sum_prop(float v) {
    uint32_t iv = __float2uint_rn(v * FIXPT);
    uint32_t r;
    asm volatile("redux.sync.add.u32 %0, %1, 0xffffffff;" : "=r"(r) : "r"(iv));
    return __uint2float_rn(r) * (1.0f / FIXPT);
}

// =====================================================================
// prolog: blocks [0, 512)    -> params, 2 elements/thread (ILP x2)
//         blocks [512, 1536) -> y[b, o] = bias[o]  (float4)
// =====================================================================
__global__ __launch_bounds__(256) void hyper_prolog(const float4* __restrict__ res4,
                                                    const float4* __restrict__ bias4,
                                                    float4*       __restrict__ y4) {
    const int b = blockIdx.x;
    const int t = threadIdx.x;
    if (b < 512) {
        const int i1 = b * 256 + t;
        const int i2 = i1 + (BATCH * KTUP) / 2;
        float4 r1 = __ldg(&res4[i1]);
        float4 r2 = __ldg(&res4[i2]);
        float4 p1, p2;
        p1.x = __fmul_rn(xla_sigmoid(r1.x), 65535.0f);
        p2.x = __fmul_rn(xla_sigmoid(r2.x), 65535.0f);
        p1.y = __fmul_rn(xla_sigmoid(r1.y), 65535.0f);
        p2.y = __fmul_rn(xla_sigmoid(r2.y), 65535.0f);
        float sg1 = (softplus_f(r1.z + 2.0f) + 1e-6f) * 65536.0f;
        float sg2 = (softplus_f(r2.z + 2.0f) + 1e-6f) * 65536.0f;
        p1.z = -0.5f / (sg1 * sg1);
        p2.z = -0.5f / (sg2 * sg2);
        p1.w = r1.w;
        p2.w = r2.w;
        g_params[i1] = p1;
        g_params[i2] = p2;
    } else {
        int i = (b - 512) * 256 + t;
        y4[i] = __ldg(&bias4[i & (DIM / 4 - 1)]);
    }
}

// =====================================================================
// main (PDL secondary): ONE warp per (b, k), lane = sample a (0..31).
// 2 hashes per lane (dim0, dim1). All warps resident on an SM share ONE
// 256KB x-row -> gather footprint fits L1 (~228KB) -> L2 traffic cut.
// Lanes 0..1 carry the 4 floor/ceil neighbors merged by out-row
// (lane = floor/ceil of m0; 2 corners each share one out index).
// =====================================================================
__global__ __launch_bounds__(256, 8) void hyper_main(const float* __restrict__ x,
                                                     float*       __restrict__ y) {
    const uint32_t w    = blockIdx.x * 8u + (threadIdx.x >> 5);   // 0 .. 262143 = b*KTUP + k
    const uint32_t lane = threadIdx.x & 31u;

    // ---- hash phase (independent of prolog; overlaps via PDL) ----
    // e(b, k, a, r) = ((b*KTUP + k)*ADDS + a)*2 + r = w*64 + lane*2 + r
    const uint32_t e0 = w * (ADDS * 2) + lane * 2u;
    const int si0 = bits_to_idx(jax_random_bits32(e0));        // dim0 (out)
    const int si1 = bits_to_idx(jax_random_bits32(e0 + 1u));   // dim1 (in)

    // ---- wait for prolog (params + y-init) ----
    cudaGridDependencySynchronize();

    // ---- params: single warp-uniform broadcast load ----
    const float4 p = __ldg(&g_params[w]);

    // ---- Gaussian prop for this lane's sample ----
    float d0 = (float)si0 - p.x;
    float d1 = (float)si1 - p.y;
    const float psamp = __expf(fmaf(d0, d0, d1 * d1) * p.z);

    // ---- neighbors: lanes 0..1, two corners (one out-row) each ----
    float pa = 0.0f, pb = 0.0f;
    int   ng0 = 0, nf1 = 0, nc1 = 0;
    if (lane < 2) {
        float g0  = (lane & 1) ? ceilf(p.x) : floorf(p.x);
        float f1v = floorf(p.y), c1v = ceilf(p.y);
        ng0 = (int)g0;  nf1 = (int)f1v;  nc1 = (int)c1v;
        float dd0 = g0 - p.x;
        float df = f1v - p.y, dc = c1v - p.y;
        pa = __expf(fmaf(dd0, dd0, df * df) * p.z);   // corner (g0, f1)
        pb = __expf(fmaf(dd0, dd0, dc * dc) * p.z);   // corner (g0, c1)
    }

    // ---- normalization: den = sum of all 36 props + P*eps ----
    const float s  = warp_sum_prop(psamp + ((lane < 2) ? pa + pb : 0.0f));
    const float sc = __fdividef(p.w, s + (float)(NP) * 1e-6f);

    // ---- gather / scatter-add (single batch row, L1-friendly) ----
    const uint32_t b = w >> 14;
    const float* xr = x + (b << 16);
    float*       yr = y + (b << 16);

    atomicAdd(yr + si0, sc * psamp * __ldg(xr + si1));
    if (lane < 2) {
        // lane-pair dedup: lane0 loads x[f1], lane1 loads x[c1], exchange
        const bool cc = (lane & 1);
        float xown = __ldg(xr + (cc ? nc1 : nf1));
        float xoth = __shfl_xor_sync(0x00000003u, xown, 1);
        float xf = cc ? xoth : xown;
        float xc = cc ? xown : xoth;
        atomicAdd(yr + ng0, sc * fmaf(pa, xf, pb * xc));
    }
}

// =====================================================================
extern "C" void kernel_launch(void* const* d_in, const int* in_sizes, int n_in,
                              void* d_out, int out_size) {
    const float*  x     = (const float*)d_in[0];          // (16, 65536)
    const float4* res4  = (const float4*)d_in[1];         // (16, 16384, 4)
    const float4* bias4 = (const float4*)d_in[2];         // (65536,)
    // d_in[3] = temp_indices: fully overwritten by learn_cols -> unused
    float* y = (float*)d_out;                             // (16, 65536)

    hyper_prolog<<<1536, 256>>>(res4, bias4, (float4*)y);

    // PDL: main may start early; it self-synchronizes via
    // cudaGridDependencySynchronize() before touching prolog outputs.
    cudaLaunchConfig_t cfg = {};
    cfg.gridDim       = dim3((BATCH * KTUP) / 8);         // 32768 blocks
    cfg.blockDim      = dim3(256);
    cfg.dynamicSmemBytes = 0;
    cfg.stream        = 0;
    cudaLaunchAttribute attrs[1];
    attrs[0].id = cudaLaunchAttributeProgrammaticStreamSerialization;
    attrs[0].val.programmaticStreamSerializationAllowed = 1;
    cfg.attrs   = attrs;
    cfg.numAttrs = 1;
    cudaLaunchKernelEx(&cfg, hyper_main, x, (float*)y);
}

// round 12
// speedup vs baseline: 1.1195x; 1.1195x over previous
#include <cuda_runtime.h>
#include <cstdint>
#include <math.h>

// ---- problem constants ----
#define BATCH    16
#define KTUP     16384
#define ADDS     32
#define NP       36          // 2^2 + 32 candidates per point
#define DIM      65536       // IN_DIM == OUT_DIM
#define KHALF    8192

// 4MB precomputed-parameter scratch: {m0, m1, nh, val} per (b, k)
__device__ float4 g_params[BATCH * KTUP];

// =====================================================================
// threefry-2x32, 20 rounds, exactly as jax._src.prng (key = (0, 42)).
// Partitionable mode: counter = (0, flat_index), bits = o0 ^ o1.
// =====================================================================
__device__ __forceinline__ void threefry2x32_42(uint32_t c0, uint32_t c1,
                                                uint32_t& o0, uint32_t& o1) {
    const uint32_t ks0 = 0u;
    const uint32_t ks1 = 42u;
    const uint32_t ks2 = 0x1BD11BDAu ^ 0u ^ 42u;
    uint32_t x0 = c0 + ks0;
    uint32_t x1 = c1 + ks1;
#define TF_R(rot) { x0 += x1; x1 = __funnelshift_l(x1, x1, rot); x1 ^= x0; }
    TF_R(13) TF_R(15) TF_R(26) TF_R(6)   x0 += ks1; x1 += ks2 + 1u;
    TF_R(17) TF_R(29) TF_R(16) TF_R(24)  x0 += ks2; x1 += ks0 + 2u;
    TF_R(13) TF_R(15) TF_R(26) TF_R(6)   x0 += ks0; x1 += ks1 + 3u;
    TF_R(17) TF_R(29) TF_R(16) TF_R(24)  x0 += ks1; x1 += ks2 + 4u;
    TF_R(13) TF_R(15) TF_R(26) TF_R(6)   x0 += ks2; x1 += ks0 + 5u;
#undef TF_R
    o0 = x0; o1 = x1;
}

__device__ __forceinline__ uint32_t jax_random_bits32(uint32_t e) {
    uint32_t o0, o1;
    threefry2x32_42(0u, e, o0, o1);
    return o0 ^ o1;
}

// bits -> JAX index, bit-exact, 1 FFMA (Sterbenz + exponent-exact scale;
// validated rounds 10-11 by identical rel_err).
__device__ __forceinline__ int bits_to_idx(uint32_t bits) {
    const float C = 0.999999f * 65536.0f;
    float v = __uint_as_float((bits >> 9) | 0x3f800000u);
    return (int)__fmaf_rn(v, C, -C);
}

// ---- sigmoid / softplus: IDENTICAL arithmetic to passing rounds 4-11 ----
__device__ __forceinline__ float xla_sigmoid(float v) {
    float e = expf(-v);
    return __fdiv_rn(1.0f, __fadd_rn(1.0f, e));
}
__device__ __forceinline__ float softplus_f(float v) {
    return fmaxf(v, 0.0f) + log1pf(__expf(-fabsf(v)));
}

// Warp sum via integer redux (f32 redux does not exist on sm_103).
// Fixed point 2^24: sum <= 36 -> max 6.0e8 < 2^31. Validated rounds 9-11.
#define FIXPT 16777216.0f
__device__ __forceinline__ float warp_sum_prop(float v) {
    uint32_t iv = __float2uint_rn(v * FIXPT);
    uint32_t r;
    asm volatile("redux.sync.add.u32 %0, %1, 0xffffffff;" : "=r"(r) : "r"(iv));
    return __uint2float_rn(r) * (1.0f / FIXPT);
}

// =====================================================================
// prolog: blocks [0, 512)    -> params, 2 elements/thread (ILP x2)
//         blocks [512, 1536) -> y[b, o] = bias[o]  (float4)
// =====================================================================
__global__ __launch_bounds__(256) void hyper_prolog(const float4* __restrict__ res4,
                                                    const float4* __restrict__ bias4,
                                                    float4*       __restrict__ y4) {
    const int b = blockIdx.x;
    const int t = threadIdx.x;
    if (b < 512) {
        const int i1 = b * 256 + t;
        const int i2 = i1 + (BATCH * KTUP) / 2;
        float4 r1 = __ldg(&res4[i1]);
        float4 r2 = __ldg(&res4[i2]);
        float4 p1, p2;
        p1.x = __fmul_rn(xla_sigmoid(r1.x), 65535.0f);
        p2.x = __fmul_rn(xla_sigmoid(r2.x), 65535.0f);
        p1.y = __fmul_rn(xla_sigmoid(r1.y), 65535.0f);
        p2.y = __fmul_rn(xla_sigmoid(r2.y), 65535.0f);
        float sg1 = (softplus_f(r1.z + 2.0f) + 1e-6f) * 65536.0f;
        float sg2 = (softplus_f(r2.z + 2.0f) + 1e-6f) * 65536.0f;
        p1.z = -0.5f / (sg1 * sg1);
        p2.z = -0.5f / (sg2 * sg2);
        p1.w = r1.w;
        p2.w = r2.w;
        g_params[i1] = p1;
        g_params[i2] = p2;
    } else {
        int i = (b - 512) * 256 + t;
        y4[i] = __ldg(&bias4[i & (DIM / 4 - 1)]);
    }
}

// =====================================================================
// main (PDL secondary): one warp per (b, kk) handling TWO points of the
// SAME batch: (b, kk) and (b, kk+8192). Same instruction count as the
// round-10 layout (4 hashes/lane, 2 param loads, 2 redux, lanes 0..3
// neighbors) but all gathers/atomics of an SM's resident warps hit ONE
// 256KB x-row -> gather footprint ~fits L1.
// =====================================================================
__global__ __launch_bounds__(256, 8) void hyper_main(const float* __restrict__ x,
                                                     float*       __restrict__ y) {
    const uint32_t w    = blockIdx.x * 8u + (threadIdx.x >> 5);   // 0 .. 131071
    const uint32_t lane = threadIdx.x & 31u;
    const uint32_t b    = w >> 13;           // 0..15
    const uint32_t kk   = w & (KHALF - 1);   // 0..8191

    const uint32_t i1 = b * KTUP + kk;       // point 1: (b, kk)
    const uint32_t i2 = i1 + KHALF;          // point 2: (b, kk+8192)

    // ---- hash phase (independent of prolog; overlaps via PDL) ----
    // e(b, k, a, r) = (idx*ADDS + a)*2 + r = idx*64 + lane*2 + r
    const uint32_t e1 = i1 * (ADDS * 2) + lane * 2u;
    const uint32_t e2 = e1 + KHALF * (ADDS * 2);     // = i2*64 + lane*2
    int si0[2], si1[2];
    si0[0] = bits_to_idx(jax_random_bits32(e1));        // point1 dim0
    si1[0] = bits_to_idx(jax_random_bits32(e1 + 1u));   // point1 dim1
    si0[1] = bits_to_idx(jax_random_bits32(e2));        // point2 dim0
    si1[1] = bits_to_idx(jax_random_bits32(e2 + 1u));   // point2 dim1

    // ---- wait for prolog (params + y-init) ----
    cudaGridDependencySynchronize();

    // ---- precomputed params (warp-uniform broadcast loads) ----
    const float4 p0 = __ldg(&g_params[i1]);
    const float4 p1 = __ldg(&g_params[i2]);

    // ---- Gaussian props for samples ----
    float psamp[2];
    {
        float d0 = (float)si0[0] - p0.x;
        float d1 = (float)si1[0] - p0.y;
        psamp[0] = __expf(fmaf(d0, d0, d1 * d1) * p0.z);
        d0 = (float)si0[1] - p1.x;
        d1 = (float)si1[1] - p1.y;
        psamp[1] = __expf(fmaf(d0, d0, d1 * d1) * p1.z);
    }

    // ---- neighbors: lanes 0..3, two corners (one out-row) each ----
    float pa = 0.0f, pb = 0.0f;
    int   ng0 = 0, nf1 = 0, nc1 = 0;
    if (lane < 4) {
        const bool hb  = lane >= 2;                 // point select
        const float mm0 = hb ? p1.x : p0.x;
        const float mm1 = hb ? p1.y : p0.y;
        const float nhh = hb ? p1.z : p0.z;
        float g0  = (lane & 1) ? ceilf(mm0) : floorf(mm0);
        float f1v = floorf(mm1), c1v = ceilf(mm1);
        ng0 = (int)g0;  nf1 = (int)f1v;  nc1 = (int)c1v;
        float d0 = g0 - mm0;
        float df = f1v - mm1, dc = c1v - mm1;
        pa = __expf(fmaf(d0, d0, df * df) * nhh);   // corner (g0, f1)
        pb = __expf(fmaf(d0, d0, dc * dc) * nhh);   // corner (g0, c1)
    }

    // ---- normalization: den = sum_p props + P*eps (integer redux) ----
    const float s0 = warp_sum_prop(psamp[0] + ((lane < 2)              ? pa + pb : 0.0f));
    const float s1 = warp_sum_prop(psamp[1] + ((lane >= 2 && lane < 4) ? pa + pb : 0.0f));
    const float sc0 = __fdividef(p0.w, s0 + (float)(NP) * 1e-6f);
    const float sc1 = __fdividef(p1.w, s1 + (float)(NP) * 1e-6f);

    // ---- gather / scatter-add: single batch row (L1-resident) ----
    const float* xr = x + (b << 16);
    float*       yr = y + (b << 16);

    atomicAdd(yr + si0[0], sc0 * psamp[0] * __ldg(xr + si1[0]));
    atomicAdd(yr + si0[1], sc1 * psamp[1] * __ldg(xr + si1[1]));
    if (lane < 4) {
        const float sc = (lane >= 2) ? sc1 : sc0;
        // lane-pair dedup: even lane loads x[f1], odd loads x[c1], exchange
        const bool cc = (lane & 1);
        float xown = __ldg(xr + (cc ? nc1 : nf1));
        float xoth = __shfl_xor_sync(0x0000000Fu, xown, 1);
        float xf = cc ? xoth : xown;
        float xc = cc ? xown : xoth;
        atomicAdd(yr + ng0, sc * fmaf(pa, xf, pb * xc));
    }
}

// =====================================================================
extern "C" void kernel_launch(void* const* d_in, const int* in_sizes, int n_in,
                              void* d_out, int out_size) {
    const float*  x     = (const float*)d_in[0];          // (16, 65536)
    const float4* res4  = (const float4*)d_in[1];         // (16, 16384, 4)
    const float4* bias4 = (const float4*)d_in[2];         // (65536,)
    // d_in[3] = temp_indices: fully overwritten by learn_cols -> unused
    float* y = (float*)d_out;                             // (16, 65536)

    hyper_prolog<<<1536, 256>>>(res4, bias4, (float4*)y);

    // PDL: main may start early; it self-synchronizes via
    // cudaGridDependencySynchronize() before touching prolog outputs.
    cudaLaunchConfig_t cfg = {};
    cfg.gridDim       = dim3((BATCH * KHALF) / 8);        // 16384 blocks
    cfg.blockDim      = dim3(256);
    cfg.dynamicSmemBytes = 0;
    cfg.stream        = 0;
    cudaLaunchAttribute attrs[1];
    attrs[0].id = cudaLaunchAttributeProgrammaticStreamSerialization;
    attrs[0].val.programmaticStreamSerializationAllowed = 1;
    cfg.attrs   = attrs;
    cfg.numAttrs = 1;
    cudaLaunchKernelEx(&cfg, hyper_main, x, (float*)y);
}

// round 13
// speedup vs baseline: 1.1211x; 1.0014x over previous
#include <cuda_runtime.h>
#include <cstdint>
#include <math.h>

// ---- problem constants ----
#define BATCH    16
#define KTUP     16384
#define ADDS     32
#define NP       36          // 2^2 + 32 candidates per point
#define DIM      65536       // IN_DIM == OUT_DIM
#define KHALF    8192
#define NPOINTS  (BATCH * KTUP)

// scratch: {m0, m1, nh, val} and {npsum, na, nb, -} per (b, k)  (4MB each)
__device__ float4 g_params[NPOINTS];
__device__ float4 g_nbr[NPOINTS];

// =====================================================================
// threefry-2x32, 20 rounds, exactly as jax._src.prng (key = (0, 42)).
// Partitionable mode: counter = (0, flat_index), bits = o0 ^ o1.
// =====================================================================
__device__ __forceinline__ void threefry2x32_42(uint32_t c0, uint32_t c1,
                                                uint32_t& o0, uint32_t& o1) {
    const uint32_t ks0 = 0u;
    const uint32_t ks1 = 42u;
    const uint32_t ks2 = 0x1BD11BDAu ^ 0u ^ 42u;
    uint32_t x0 = c0 + ks0;
    uint32_t x1 = c1 + ks1;
#define TF_R(rot) { x0 += x1; x1 = __funnelshift_l(x1, x1, rot); x1 ^= x0; }
    TF_R(13) TF_R(15) TF_R(26) TF_R(6)   x0 += ks1; x1 += ks2 + 1u;
    TF_R(17) TF_R(29) TF_R(16) TF_R(24)  x0 += ks2; x1 += ks0 + 2u;
    TF_R(13) TF_R(15) TF_R(26) TF_R(6)   x0 += ks0; x1 += ks1 + 3u;
    TF_R(17) TF_R(29) TF_R(16) TF_R(24)  x0 += ks1; x1 += ks2 + 4u;
    TF_R(13) TF_R(15) TF_R(26) TF_R(6)   x0 += ks2; x1 += ks0 + 5u;
#undef TF_R
    o0 = x0; o1 = x1;
}

__device__ __forceinline__ uint32_t jax_random_bits32(uint32_t e) {
    uint32_t o0, o1;
    threefry2x32_42(0u, e, o0, o1);
    return o0 ^ o1;
}

// bits -> JAX index, bit-exact, 1 FFMA (validated rounds 10-12).
__device__ __forceinline__ int bits_to_idx(uint32_t bits) {
    const float C = 0.999999f * 65536.0f;
    float v = __uint_as_float((bits >> 9) | 0x3f800000u);
    return (int)__fmaf_rn(v, C, -C);
}

// ---- sigmoid / softplus: IDENTICAL arithmetic to passing rounds 4-12 ----
__device__ __forceinline__ float xla_sigmoid(float v) {
    float e = expf(-v);
    return __fdiv_rn(1.0f, __fadd_rn(1.0f, e));
}
__device__ __forceinline__ float softplus_f(float v) {
    return fmaxf(v, 0.0f) + log1pf(__expf(-fabsf(v)));
}

// Warp sum via integer redux. Fixed point 2^24: sum <= 36 -> < 2^31.
#define FIXPT 16777216.0f
__device__ __forceinline__ float warp_sum_prop(float v) {
    uint32_t iv = __float2uint_rn(v * FIXPT);
    uint32_t r;
    asm volatile("redux.sync.add.u32 %0, %1, 0xffffffff;" : "=r"(r) : "r"(iv));
    return __uint2float_rn(r) * (1.0f / FIXPT);
}

// Per-point param + neighbor precompute. Op sequences replicate the
// passing round-12 main-kernel neighbor path EXACTLY (bit-identical).
__device__ __forceinline__ void point_precompute(const float* __restrict__ x,
                                                 float4 r, int idx,
                                                 float4& p, float4& nb4) {
    p.x = __fmul_rn(xla_sigmoid(r.x), 65535.0f);     // m0
    p.y = __fmul_rn(xla_sigmoid(r.y), 65535.0f);     // m1
    float sg = (softplus_f(r.z + 2.0f) + 1e-6f) * 65536.0f;
    p.z = -0.5f / (sg * sg);                         // nh
    p.w = r.w;                                       // val

    const float* xr = x + ((idx >> 14) << 16);       // batch row
    float f0v = floorf(p.x), c0v = ceilf(p.x);
    float f1v = floorf(p.y), c1v = ceilf(p.y);
    float df = f1v - p.y, dc = c1v - p.y;
    // out-row floor(m0): corners (f0, f1), (f0, c1)
    float d0a = f0v - p.x;
    float paa = __expf(fmaf(d0a, d0a, df * df) * p.z);
    float pab = __expf(fmaf(d0a, d0a, dc * dc) * p.z);
    // out-row ceil(m0): corners (c0, f1), (c0, c1)
    float d0b = c0v - p.x;
    float pba = __expf(fmaf(d0b, d0b, df * df) * p.z);
    float pbb = __expf(fmaf(d0b, d0b, dc * dc) * p.z);

    float xf = __ldg(xr + (int)f1v);
    float xc = __ldg(xr + (int)c1v);
    nb4.x = (paa + pab) + (pba + pbb);               // npsum
    nb4.y = fmaf(paa, xf, pab * xc);                 // numerator @ floor(m0)
    nb4.z = fmaf(pba, xf, pbb * xc);                 // numerator @ ceil(m0)
    nb4.w = 0.0f;
}

// =====================================================================
// prolog: blocks [0, 512)    -> params + neighbor precompute, ILP x2
//         blocks [512, 1536) -> y[b, o] = bias[o]  (float4)
// =====================================================================
__global__ __launch_bounds__(256) void hyper_prolog(const float*  __restrict__ x,
                                                    const float4* __restrict__ res4,
                                                    const float4* __restrict__ bias4,
                                                    float4*       __restrict__ y4) {
    const int b = blockIdx.x;
    const int t = threadIdx.x;
    if (b < 512) {
        const int i1 = b * 256 + t;
        const int i2 = i1 + NPOINTS / 2;
        float4 r1 = __ldg(&res4[i1]);
        float4 r2 = __ldg(&res4[i2]);
        float4 p1, p2, n1, n2;
        point_precompute(x, r1, i1, p1, n1);
        point_precompute(x, r2, i2, p2, n2);
        g_params[i1] = p1;  g_nbr[i1] = n1;
        g_params[i2] = p2;  g_nbr[i2] = n2;
    } else {
        int i = (b - 512) * 256 + t;
        y4[i] = __ldg(&bias4[i & (DIM / 4 - 1)]);
    }
}

// =====================================================================
// main (PDL secondary): one warp per (b, kk) handling (b, kk) and
// (b, kk+8192). Neighbor math fully hoisted to prolog: lanes 0..3 just
// fire one precomputed-numerator atomic each; lanes 0/2 fold npsum into
// the fixed-point warp sum.
// =====================================================================
__global__ __launch_bounds__(256, 8) void hyper_main(const float* __restrict__ x,
                                                     float*       __restrict__ y) {
    const uint32_t w    = blockIdx.x * 8u + (threadIdx.x >> 5);   // 0 .. 131071
    const uint32_t lane = threadIdx.x & 31u;
    const uint32_t b    = w >> 13;           // 0..15
    const uint32_t kk   = w & (KHALF - 1);   // 0..8191

    const uint32_t i1 = b * KTUP + kk;       // point 1: (b, kk)
    const uint32_t i2 = i1 + KHALF;          // point 2: (b, kk+8192)

    // ---- hash phase (independent of prolog; overlaps via PDL) ----
    const uint32_t e1 = i1 * (ADDS * 2) + lane * 2u;
    const uint32_t e2 = e1 + KHALF * (ADDS * 2);
    int si0[2], si1[2];
    si0[0] = bits_to_idx(jax_random_bits32(e1));        // point1 dim0
    si1[0] = bits_to_idx(jax_random_bits32(e1 + 1u));   // point1 dim1
    si0[1] = bits_to_idx(jax_random_bits32(e2));        // point2 dim0
    si1[1] = bits_to_idx(jax_random_bits32(e2 + 1u));   // point2 dim1

    // ---- wait for prolog (params + neighbors + y-init) ----
    cudaGridDependencySynchronize();

    // ---- precomputed data (warp-uniform broadcast loads) ----
    const float4 p0 = __ldg(&g_params[i1]);
    const float4 p1 = __ldg(&g_params[i2]);
    const float4 n0 = __ldg(&g_nbr[i1]);
    const float4 n1 = __ldg(&g_nbr[i2]);

    // ---- Gaussian props for samples ----
    float psamp[2];
    {
        float d0 = (float)si0[0] - p0.x;
        float d1 = (float)si1[0] - p0.y;
        psamp[0] = __expf(fmaf(d0, d0, d1 * d1) * p0.z);
        d0 = (float)si0[1] - p1.x;
        d1 = (float)si1[1] - p1.y;
        psamp[1] = __expf(fmaf(d0, d0, d1 * d1) * p1.z);
    }

    // ---- normalization: den = sum_p props + P*eps (integer redux) ----
    const float s0 = warp_sum_prop(psamp[0] + ((lane == 0) ? n0.x : 0.0f));
    const float s1 = warp_sum_prop(psamp[1] + ((lane == 2) ? n1.x : 0.0f));
    const float sc0 = __fdividef(p0.w, s0 + (float)(NP) * 1e-6f);
    const float sc1 = __fdividef(p1.w, s1 + (float)(NP) * 1e-6f);

    // ---- gather / scatter-add: single batch row ----
    const float* xr = x + (b << 16);
    float*       yr = y + (b << 16);

    atomicAdd(yr + si0[0], sc0 * psamp[0] * __ldg(xr + si1[0]));
    atomicAdd(yr + si0[1], sc1 * psamp[1] * __ldg(xr + si1[1]));
    if (lane < 4) {
        const bool hb = lane >= 2;                    // point select
        const float px  = hb ? p1.x : p0.x;
        const float sc  = hb ? sc1 : sc0;
        const float num = (lane & 1) ? (hb ? n1.z : n0.z)   // @ceil(m0)
                                     : (hb ? n1.y : n0.y);  // @floor(m0)
        const int   row = (lane & 1) ? (int)ceilf(px) : (int)floorf(px);
        atomicAdd(yr + row, sc * num);
    }
}

// =====================================================================
extern "C" void kernel_launch(void* const* d_in, const int* in_sizes, int n_in,
                              void* d_out, int out_size) {
    const float*  x     = (const float*)d_in[0];          // (16, 65536)
    const float4* res4  = (const float4*)d_in[1];         // (16, 16384, 4)
    const float4* bias4 = (const float4*)d_in[2];         // (65536,)
    // d_in[3] = temp_indices: fully overwritten by learn_cols -> unused
    float* y = (float*)d_out;                             // (16, 65536)

    hyper_prolog<<<1536, 256>>>(x, res4, bias4, (float4*)y);

    // PDL: main may start early; it self-synchronizes via
    // cudaGridDependencySynchronize() before touching prolog outputs.
    cudaLaunchConfig_t cfg = {};
    cfg.gridDim       = dim3((BATCH * KHALF) / 8);        // 16384 blocks
    cfg.blockDim      = dim3(256);
    cfg.dynamicSmemBytes = 0;
    cfg.stream        = 0;
    cudaLaunchAttribute attrs[1];
    attrs[0].id = cudaLaunchAttributeProgrammaticStreamSerialization;
    attrs[0].val.programmaticStreamSerializationAllowed = 1;
    cfg.attrs   = attrs;
    cfg.numAttrs = 1;
    cudaLaunchKernelEx(&cfg, hyper_main, x, (float*)y);
}